// round 9
// baseline (speedup 1.0000x reference)
#include <cuda_runtime.h>

// DTWLoss B=64, T=1024. Warp-pipelined column-sweep DP with fused path loss.
// 2 CTAs per batch (rows 0-511 / 512-1023), 8 warps x 32 lanes x 2 rows each.
// 16-stage pipeline: intra-CTA via smem rings + named barriers, cross-CTA via
// gmem boundary + self-resetting acquire/release flags. This revision:
// FMNMX-chain recurrence (short c-chain), software-pipelined LDS, bare SHFL.

#define Tn 1024
#define Bn 64
#define CW 32
#define NWARP 8
#define NTH 256
#define INFV 1e30f

__device__ float2   g_bnd[Bn][Tn + 64];    // row-511 boundary; +32 front pad
__device__ unsigned g_flag[Bn][32];        // per-chunk ready flags (self-reset)
__device__ float2   g_dummy[2 * Bn][32];   // gmem store sink (lo warp7, lanes!=31)
__device__ float    g_losses[Bn];
__device__ unsigned g_count;               // zero-init; last CTA resets

__device__ __forceinline__ unsigned ld_acq(const unsigned* p) {
    unsigned v;
    asm volatile("ld.acquire.gpu.u32 %0, [%1];" : "=r"(v) : "l"(p) : "memory");
    return v;
}
__device__ __forceinline__ void st_rel(unsigned* p, unsigned v) {
    asm volatile("st.release.gpu.u32 [%0], %1;" :: "l"(p), "r"(v) : "memory");
}
__device__ __forceinline__ float fsqrt_ap(float x) {
    float r;
    asm("sqrt.approx.f32 %0, %1;" : "=f"(r) : "f"(x));
    return r;
}
__device__ __forceinline__ float shfl_up1(float v) {
    unsigned r, a = __float_as_uint(v);
    asm volatile("shfl.sync.up.b32 %0, %1, 1, 0x0, 0xffffffff;" : "=r"(r) : "r"(a));
    return __uint_as_float(r);
}
#define BARSYNC(id) asm volatile("bar.sync %0, 64;" :: "r"(id) : "memory")

// One 32(or 31)-step chunk. GOUT: boundary store goes to gmem (lo warp7).
template<int NSTEPS, bool GOUT>
__device__ __forceinline__ void run_chunk(
    int s0, bool is_lane0, bool is_lane31,
    const float2* __restrict__ bp, const float2* __restrict__ qp,
    float2* outp, int msk, float2* sinkp,
    float px0, float py0, float px1, float py1, float sc0, float sc1,
    float& c0, float& c1, float& L0, float& L1,
    float& upc, float& upL, float& p_uc, float& p_uL)
{
    float2 bv = bp[0];
    float2 q  = qp[0];
#pragma unroll 4
    for (int k = 0; k < NSTEPS; ++k) {
        // software-pipelined loads for next step (one-past-end reads are safe)
        const float2 bvn = bp[k + 1];
        const float2 qn  = qp[k + 1];

        const float uc = is_lane0 ? bv.x : upc;
        const float uL = is_lane0 ? bv.y : upL;

        // distances + L-increments for both rows (off-chain, ILP)
        const float dx0 = px0 - q.x, dy0 = py0 - q.y;
        const float dx1 = px1 - q.x, dy1 = py1 - q.y;
        const float d0 = fsqrt_ap(fmaf(dx0, dx0, dy0 * dy0));
        const float d1 = fsqrt_ap(fmaf(dx1, dx1, dy1 * dy1));
        const float e0 = fmaf(fabsf(dx0), sc0, fabsf(dy0) * sc1);
        const float e1 = fmaf(fabsf(dx1), sc0, fabsf(dy1) * sc1);

        const float lc0 = c0, lL0 = L0, lc1 = c1, lL1 = L1;

        // row 0: diag=p_uc, up=uc, left=lc0  (tie order: diag, up, left)
        const float mul0 = fminf(uc, lc0);
        const bool  pd0  = (p_uc <= mul0);
        const bool  pu0  = (uc <= lc0);
        c0 = d0 + fminf(p_uc, mul0);
        L0 = e0 + (pd0 ? p_uL : (pu0 ? uL : lL0));

        // row 1: diag=lc0(old), up=c0(new), left=lc1
        const float mul1 = fminf(c0, lc1);
        const bool  pd1  = (lc0 <= mul1);
        const bool  pu1  = (c0 <= lc1);
        c1 = d1 + fminf(lc0, mul1);
        L1 = e1 + (pd1 ? lL0 : (pu1 ? L0 : lL1));

        p_uc = uc; p_uL = uL;

        // branch-free boundary store (lane31 -> real target, others -> sink)
        const int j = s0 + k - 31;
        float2* sta;
        if (GOUT) sta = is_lane31 ? (outp + j) : sinkp;          // STG.64
        else      sta = is_lane31 ? (outp + (j & msk)) : sinkp;  // STS.64
        *sta = make_float2(c1, L1);

        // lane handoff for next step
        upc = shfl_up1(c1);
        upL = shfl_up1(L1);

        bv = bvn; q = qn;
    }
}

__global__ void __launch_bounds__(NTH, 1)
dtw_kernel(const float* __restrict__ preds,
           const float* __restrict__ targs,
           const float* __restrict__ subcoef,
           float* __restrict__ out)
{
    __shared__ float2 sq_full[32 + Tn + 64];   // padded target coords
    __shared__ float2 bnd[NWARP - 1][132];     // 4-deep chunk rings (+4 overread pad)
    __shared__ float2 sHB[132];                // staged cross-CTA chunks (hi warp0)
    __shared__ float2 sINF[132];               // INF boundary (lo warp0)
    __shared__ float2 sink7[32];               // hi warp7 boundary dump ring
    __shared__ float2 scratch[NTH];            // smem store sink

    const int b    = blockIdx.x >> 1;
    const int hi   = blockIdx.x & 1;
    const int t    = threadIdx.x;
    const int lane = t & 31;
    const int warp = t >> 5;
    const int rowbase = hi * 512 + warp * 64 + lane * 2;

    // ---- stage inputs ----
    const float* tb = targs + (size_t)b * Tn * 4;
    for (int j = t; j < Tn; j += NTH) {
        float4 v = *(const float4*)(tb + j * 4);
        sq_full[32 + j] = make_float2(v.x, v.y);
    }
    if (t < 32)  sq_full[t] = make_float2(0.f, 0.f);
    if (t < 64)  sq_full[32 + Tn + t] = make_float2(0.f, 0.f);
    if (t < 132) sINF[t] = make_float2(INFV, 0.f);

    const float* pb = preds + (size_t)b * Tn * 4;
    float4 p0 = *(const float4*)(pb + (size_t)rowbase * 4);
    float4 p1 = *(const float4*)(pb + (size_t)(rowbase + 1) * 4);
    const float px0 = p0.x, py0 = p0.y, px1 = p1.x, py1 = p1.y;
    const float sc0 = subcoef[0];
    const float sc1 = subcoef[1];

    float c0 = INFV, c1 = INFV, L0 = 0.f, L1 = 0.f;
    if (!hi && t == 0) c0 = 0.f;        // virtual C(0,-1)=0 -> C(0,0)=D(0,0)
    float upc = INFV, upL = 0.f;        // shfl result pipeline
    float p_uc = INFV, p_uL = 0.f;      // previous step's up = diag source

    const bool is_lane0  = (lane == 0);
    const bool is_lane31 = (lane == 31);
    const bool gout = (warp == NWARP - 1) && !hi;

    // lane0 boundary-read source
    const float2* bsrc = (warp == 0) ? (hi ? sHB : sINF) : bnd[warp - 1];
    // lane31 boundary-write target
    float2* outp;
    int msk;
    if (warp < NWARP - 1) { outp = bnd[warp]; msk = 127; }
    else if (hi)          { outp = sink7;     msk = 31; }
    else                  { outp = g_bnd[b] + 32; msk = -1; }
    float2* sinkp = gout ? &g_dummy[blockIdx.x][lane] : &scratch[t];

    __syncthreads();

    for (int cc = 0; cc <= 32; ++cc) {
        const int s0 = cc * CW;
        // ---- prologue: consumer waits for producer stage ----
        if (cc < 32) {
            if (warp == 0) {
                if (hi) {
                    unsigned* fp = &g_flag[b][cc];
                    if (is_lane0) { while (ld_acq(fp) == 0u) {} }
                    __syncwarp();
                    float2 v = __ldcg(&g_bnd[b][32 + s0 + lane]);
                    sHB[((cc & 3) << 5) + lane] = v;
                    if (is_lane0) *(volatile unsigned*)fp = 0u;   // self-reset
                    __syncwarp();
                }
            } else {
                BARSYNC(warp);
            }
        }

        const float2* bp = bsrc + ((cc & 3) << 5);
        const float2* qp = sq_full + 32 + s0 - lane;

        if (gout) {
            if (cc < 32) run_chunk<32, true >(s0, is_lane0, is_lane31, bp, qp, outp, msk, sinkp,
                                              px0, py0, px1, py1, sc0, sc1, c0, c1, L0, L1, upc, upL, p_uc, p_uL);
            else         run_chunk<31, true >(s0, is_lane0, is_lane31, bp, qp, outp, msk, sinkp,
                                              px0, py0, px1, py1, sc0, sc1, c0, c1, L0, L1, upc, upL, p_uc, p_uL);
        } else {
            if (cc < 32) run_chunk<32, false>(s0, is_lane0, is_lane31, bp, qp, outp, msk, sinkp,
                                              px0, py0, px1, py1, sc0, sc1, c0, c1, L0, L1, upc, upL, p_uc, p_uL);
            else         run_chunk<31, false>(s0, is_lane0, is_lane31, bp, qp, outp, msk, sinkp,
                                              px0, py0, px1, py1, sc0, sc1, c0, c1, L0, L1, upc, upL, p_uc, p_uL);
        }

        // ---- epilogue: producer release (chunk cc done -> consumer may run cc-1) ----
        if (cc >= 1) {
            if (warp < NWARP - 1) {
                BARSYNC(warp + 1);
            } else if (!hi) {
                if (is_lane31) st_rel(&g_flag[b][cc - 1], 1u);
            }
        }
    }

    // ---- fused reduction: hi CTAs only ----
    if (hi && t == NTH - 1) {
        g_losses[b] = L1;                 // row 1023, col 1023 (last real step)
        __threadfence();
        unsigned old = atomicAdd(&g_count, 1u);
        if (old == Bn - 1) {
            __threadfence();
            float s = 0.f;
            const volatile float* gl = g_losses;
#pragma unroll 8
            for (int i = 0; i < Bn; ++i) s += gl[i];
            out[0] = s;
            g_count = 0;                  // reset for next graph replay
        }
    }
}

extern "C" void kernel_launch(void* const* d_in, const int* in_sizes, int n_in,
                              void* d_out, int out_size)
{
    const float* preds   = (const float*)d_in[0];
    const float* targs   = (const float*)d_in[1];
    const float* subcoef = (const float*)d_in[2];
    float* out = (float*)d_out;

    dtw_kernel<<<2 * Bn, NTH>>>(preds, targs, subcoef, out);
}